// round 11
// baseline (speedup 1.0000x reference)
#include <cuda_runtime.h>
#include <math.h>

// VectorQuantizer: N=65536 (64x32x32 BHWC-flat), C=64, K=1024.
// Output (float32): [quantized 4194304][vq_loss 1][indices 65536][perplexity 1]
// Numerics verified bit-exact R1/R5/R7/R9/R10.
// R11: E pre-duplicated along channels in global (g_edup), cp.async-staged
// verbatim -> inner loop has ZERO dup MOVs (was 32 MOV32 per c4-iter).

#define NPTS   65536
#define KC     1024
#define CD     64
#define HW     1024
#define MT     128
#define KCH    64
#define NCH    (KC / KCH)     // 16 chunks
#define XSTRIDE 132
#define EPITCH  132           // es pitch: [code][2c] duplicated channels + pad

#define SM_XS   0
#define SM_ES   (CD * XSTRIDE)           // 8448
#define SM_AS   (SM_ES + KCH * EPITCH)   // +8448 = 16896
#define SM_IDX  (SM_AS + 128)
#define SMEM_FLOATS (SM_IDX + 128)       // 17152 floats = 68,608 B -> 2 blocks/SM
#define SMEM_BYTES  (SMEM_FLOATS * 4)

#define OFF_LOSS  4194304
#define OFF_IDX   4194305
#define OFF_PERP  4259841

typedef unsigned long long u64;
typedef unsigned int u32;

__device__ float        g_esq[KC];
__device__ float        g_edup[KC * 128];   // [k][2c] = [k][2c+1] = e[k][c]
__device__ unsigned int g_hist[KC];
__device__ double       g_loss;

__device__ __forceinline__ void unpack2(u64 v, float &lo, float &hi) {
    asm("mov.b64 {%0, %1}, %2;" : "=f"(lo), "=f"(hi) : "l"(v));
}
// packed fp32x2 FMA: each lane is IEEE-rn fp32 FMA (bit-identical to scalar FFMA)
__device__ __forceinline__ void ffma2(u64 &acc, u64 a, u64 b) {
    asm("fma.rn.f32x2 %0, %1, %2, %0;" : "+l"(acc) : "l"(a), "l"(b));
}
__device__ __forceinline__ u32 smem_u32(const void* p) {
    u32 a; asm("{ .reg .u64 t; cvta.to.shared.u64 t, %1; cvt.u32.u64 %0, t; }" : "=r"(a) : "l"(p));
    return a;
}
__device__ __forceinline__ void cp16(u32 dst, const void* src) {
    asm volatile("cp.async.cg.shared.global [%0], [%1], 16;" :: "r"(dst), "l"(src));
}
__device__ __forceinline__ void cp_commit() {
    asm volatile("cp.async.commit_group;" ::: "memory");
}
__device__ __forceinline__ void cp_wait0() {
    asm volatile("cp.async.wait_group 0;" ::: "memory");
}

// ---------------- init ----------------
__global__ void vq_init_hist() {
    int t = blockIdx.x * blockDim.x + threadIdx.x;
    if (t < KC) g_hist[t] = 0u;
    if (t == 0) g_loss = 0.0;
}

// ---------------- esq ----------------
__global__ void vq_esq(const float* __restrict__ emb) {
    int k = blockIdx.x * blockDim.x + threadIdx.x;
    if (k < KC) {
        float s = 0.0f;
        const float* er = emb + (size_t)k * CD;
        #pragma unroll
        for (int c = 0; c < CD; ++c) {
            float e = er[c];
            s = __fadd_rn(s, __fmul_rn(e, e));
        }
        g_esq[k] = s;
    }
}

// ---------------- build channel-duplicated codebook ----------------
__global__ void vq_edup(const float* __restrict__ emb) {
    int tid = blockIdx.x * blockDim.x + threadIdx.x;   // 65,536
    int k = tid >> 6;
    int c = tid & 63;
    float v = emb[(size_t)k * CD + c];
    *reinterpret_cast<float2*>(&g_edup[(size_t)k * 128 + 2 * c]) = make_float2(v, v);
}

// ------- fused: distances + argmin + quantize + loss + hist -------
__global__ void __launch_bounds__(256) vq_main(const float* __restrict__ inputs,
                                               const float* __restrict__ emb,
                                               float* __restrict__ out) {
    extern __shared__ float sm[];
    float* xs   = sm + SM_XS;    // [CD][XSTRIDE]  xs[c*XSTRIDE + p]
    float* es   = sm + SM_ES;    // [KCH][EPITCH]  duplicated E chunk
    float* as_  = sm + SM_AS;    // [128] ||x||^2
    int*   idxs = (int*)(sm + SM_IDX);
    double* red = (double*)es;   // tail scratch (es dead then)

    const int t  = threadIdx.x;
    const int tr = t >> 4;    // 0..15 point group (8 pts each)
    const int tc = t & 15;    // 0..15 code lane (codes j*16+tc)
    const int n0 = blockIdx.x * MT;
    const int b  = n0 >> 10;
    const int p0 = n0 & 1023;
    const float* xbase = inputs + (size_t)b * (CD * HW) + p0;

    const u32 es_base = smem_u32(es);
    // staging slot: q = t + 256*j -> row = q>>5 (0..63), col4 = q&31
    const int srow = t >> 5;
    const int scol = (t & 31) << 2;

    // ---- load x tile (transposed into [c][p])
    #pragma unroll
    for (int j = 0; j < 8; ++j) {
        int q  = t + j * 256;
        int c  = q >> 5;
        int i4 = (q & 31) << 2;
        float4 v = *reinterpret_cast<const float4*>(xbase + (size_t)c * HW + i4);
        *reinterpret_cast<float4*>(&xs[c * XSTRIDE + i4]) = v;
    }
    __syncthreads();

    // a = ||x||^2 : strictly sequential fp32
    if (t < MT) {
        float s = 0.0f;
        #pragma unroll
        for (int c = 0; c < CD; ++c) {
            float xv = xs[c * XSTRIDE + t];
            s = __fadd_rn(s, __fmul_rn(xv, xv));
        }
        as_[t] = s;
    }

    float bestv[8];
    int   besti[8];
    #pragma unroll
    for (int i = 0; i < 8; ++i) { bestv[i] = __int_as_float(0x7f800000); besti[i] = 0x7fffffff; }

    const float* xr = xs + 8 * tr;

    #pragma unroll 1
    for (int kc = 0; kc < NCH; ++kc) {
        __syncthreads();   // prior readers of es done (covers xs/as_ first iter)
        // stage duplicated E chunk verbatim from g_edup (8 cp16/thread)
        {
            const float* src = g_edup + (size_t)(kc * KCH + srow) * 128 + scol;
            u32 dst = es_base + (u32)(srow * EPITCH + scol) * 4u;
            #pragma unroll
            for (int j = 0; j < 8; ++j) {
                cp16(dst + (u32)(j * 8 * EPITCH) * 4u, src + (size_t)j * 8 * 128);
            }
        }
        cp_commit();
        cp_wait0();
        __syncthreads();   // es visible to all

        // prefetch esq for this lane's 4 codes (consumed ~2000 cyc later)
        float esq0 = __ldg(&g_esq[kc * KCH + tc]);
        float esq1 = __ldg(&g_esq[kc * KCH + 16 + tc]);
        float esq2 = __ldg(&g_esq[kc * KCH + 32 + tc]);
        float esq3 = __ldg(&g_esq[kc * KCH + 48 + tc]);

        u64 acc[4][4];     // [code j][point pair i]
        #pragma unroll
        for (int j = 0; j < 4; ++j)
            #pragma unroll
            for (int i = 0; i < 4; ++i) acc[j][i] = 0ULL;

        #pragma unroll 4
        for (int c4 = 0; c4 < CD; c4 += 4) {
            // X: 4 cc-steps x 4 natural point pairs (broadcast across tc)
            ulonglong2 Xa0 = *reinterpret_cast<const ulonglong2*>(xr + (c4 + 0) * XSTRIDE);
            ulonglong2 Xb0 = *reinterpret_cast<const ulonglong2*>(xr + (c4 + 0) * XSTRIDE + 4);
            ulonglong2 Xa1 = *reinterpret_cast<const ulonglong2*>(xr + (c4 + 1) * XSTRIDE);
            ulonglong2 Xb1 = *reinterpret_cast<const ulonglong2*>(xr + (c4 + 1) * XSTRIDE + 4);
            ulonglong2 Xa2 = *reinterpret_cast<const ulonglong2*>(xr + (c4 + 2) * XSTRIDE);
            ulonglong2 Xb2 = *reinterpret_cast<const ulonglong2*>(xr + (c4 + 2) * XSTRIDE + 4);
            ulonglong2 Xa3 = *reinterpret_cast<const ulonglong2*>(xr + (c4 + 3) * XSTRIDE);
            ulonglong2 Xb3 = *reinterpret_cast<const ulonglong2*>(xr + (c4 + 3) * XSTRIDE + 4);
            #pragma unroll
            for (int j = 0; j < 4; ++j) {
                const float* erow = es + (j * 16 + tc) * EPITCH + 2 * c4;
                ulonglong2 Elo = *reinterpret_cast<const ulonglong2*>(erow);     // (e_c4,e_c4),(e_c4+1,e_c4+1)
                ulonglong2 Ehi = *reinterpret_cast<const ulonglong2*>(erow + 4); // (e_c4+2,..),(e_c4+3,..)
                ffma2(acc[j][0], Elo.x, Xa0.x); ffma2(acc[j][1], Elo.x, Xa0.y);
                ffma2(acc[j][2], Elo.x, Xb0.x); ffma2(acc[j][3], Elo.x, Xb0.y);
                ffma2(acc[j][0], Elo.y, Xa1.x); ffma2(acc[j][1], Elo.y, Xa1.y);
                ffma2(acc[j][2], Elo.y, Xb1.x); ffma2(acc[j][3], Elo.y, Xb1.y);
                ffma2(acc[j][0], Ehi.x, Xa2.x); ffma2(acc[j][1], Ehi.x, Xa2.y);
                ffma2(acc[j][2], Ehi.x, Xb2.x); ffma2(acc[j][3], Ehi.x, Xb2.y);
                ffma2(acc[j][0], Ehi.y, Xa3.x); ffma2(acc[j][1], Ehi.y, Xa3.y);
                ffma2(acc[j][2], Ehi.y, Xb3.x); ffma2(acc[j][3], Ehi.y, Xb3.y);
            }
        }

        // epilogue: d = (a - 2*dot) + esq; k ascending per lane -> strict '<'
        #pragma unroll
        for (int j = 0; j < 4; ++j) {
            int k = kc * KCH + j * 16 + tc;
            float esq = (j == 0) ? esq0 : (j == 1) ? esq1 : (j == 2) ? esq2 : esq3;
            #pragma unroll
            for (int i = 0; i < 4; ++i) {
                float d0, d1; unpack2(acc[j][i], d0, d1);
                int ii = i * 2;
                float a0 = as_[tr * 8 + ii];
                float a1 = as_[tr * 8 + ii + 1];
                float dd0 = __fadd_rn(__fsub_rn(a0, __fmul_rn(2.0f, d0)), esq);
                float dd1 = __fadd_rn(__fsub_rn(a1, __fmul_rn(2.0f, d1)), esq);
                if (dd0 < bestv[ii])     { bestv[ii]     = dd0; besti[ii]     = k; }
                if (dd1 < bestv[ii + 1]) { bestv[ii + 1] = dd1; besti[ii + 1] = k; }
            }
        }
    }

    // cross-lane argmin over the 16 code lanes (first-index ties)
    #pragma unroll
    for (int off = 1; off < 16; off <<= 1) {
        #pragma unroll
        for (int i = 0; i < 8; ++i) {
            float ov = __shfl_xor_sync(0xffffffffu, bestv[i], off);
            int   oi = __shfl_xor_sync(0xffffffffu, besti[i], off);
            if (ov < bestv[i] || (ov == bestv[i] && oi < besti[i])) { bestv[i] = ov; besti[i] = oi; }
        }
    }
    if (tc == 0) {
        #pragma unroll
        for (int i = 0; i < 8; ++i) {
            int p = tr * 8 + i;
            idxs[p] = besti[i];
            out[OFF_IDX + n0 + p] = (float)besti[i];
            atomicAdd(&g_hist[besti[i]], 1u);
        }
    }
    __syncthreads();   // idxs visible; mainloop smem readers done

    // ---- fused quantize + straight-through + loss (xs still resident) ----
    {
        const int p = t >> 1;
        const int h = t & 1;
        const int c0 = 32 * h;
        const int k = idxs[p];
        const float* eb = emb + (size_t)k * CD + c0;
        float* ob = out + (size_t)(n0 + p) * CD + c0;
        const float* xcol = xs + c0 * XSTRIDE + p;

        double s = 0.0;
        #pragma unroll
        for (int j = 0; j < 8; ++j) {
            float4 qv = __ldg(reinterpret_cast<const float4*>(eb) + j);
            float x0 = xcol[(4 * j + 0) * XSTRIDE];
            float x1 = xcol[(4 * j + 1) * XSTRIDE];
            float x2 = xcol[(4 * j + 2) * XSTRIDE];
            float x3 = xcol[(4 * j + 3) * XSTRIDE];
            float e0 = __fsub_rn(qv.x, x0);
            float e1 = __fsub_rn(qv.y, x1);
            float e2 = __fsub_rn(qv.z, x2);
            float e3 = __fsub_rn(qv.w, x3);
            float4 o;  // straight-through: x + (q - x)
            o.x = __fadd_rn(x0, e0);
            o.y = __fadd_rn(x1, e1);
            o.z = __fadd_rn(x2, e2);
            o.w = __fadd_rn(x3, e3);
            *reinterpret_cast<float4*>(ob + 4 * j) = o;
            s += (double)__fmul_rn(e0, e0) + (double)__fmul_rn(e1, e1)
               + (double)__fmul_rn(e2, e2) + (double)__fmul_rn(e3, e3);
        }
        #pragma unroll
        for (int off = 16; off > 0; off >>= 1)
            s += __shfl_down_sync(0xffffffffu, s, off);
        if ((t & 31) == 0) red[t >> 5] = s;
        __syncthreads();
        if (t == 0) {
            double tot = 0.0;
            #pragma unroll
            for (int w = 0; w < 8; ++w) tot += red[w];
            atomicAdd(&g_loss, tot);
        }
    }
}

// ---------------- finalize ----------------
__global__ void vq_final(float* __restrict__ out) {
    __shared__ double red[256];
    int t = threadIdx.x;
    double s = 0.0;
    for (int k = t; k < KC; k += 256) {
        float cnt = (float)g_hist[k];
        float pr  = __fmul_rn(cnt, 1.0f / 65536.0f);
        float lg  = logf(__fadd_rn(pr, 1e-10f));
        s += (double)__fmul_rn(pr, lg);
    }
    red[t] = s;
    __syncthreads();
    for (int off = 128; off > 0; off >>= 1) {
        if (t < off) red[t] += red[t + off];
        __syncthreads();
    }
    if (t == 0) {
        float m = (float)(g_loss / 4194304.0);
        out[OFF_LOSS] = __fadd_rn(m, __fmul_rn(0.25f, m));
        out[OFF_PERP] = expf(-(float)red[0]);
    }
}

extern "C" void kernel_launch(void* const* d_in, const int* in_sizes, int n_in,
                              void* d_out, int out_size) {
    const float* inputs = (const float*)d_in[0];
    const float* emb    = (const float*)d_in[1];
    if (n_in >= 2 && in_sizes[0] == KC * CD && in_sizes[1] == NPTS * CD) {
        const float* tmp = inputs; inputs = emb; emb = tmp;
    }
    float* out = (float*)d_out;

    cudaFuncSetAttribute(vq_main, cudaFuncAttributeMaxDynamicSharedMemorySize, SMEM_BYTES);

    // launch order keeps vq_main at launch index 3 (ncu captures idx 3)
    vq_init_hist<<<1, 1024>>>();
    vq_esq<<<KC / 256, 256>>>(emb);
    vq_edup<<<256, 256>>>(emb);
    vq_main<<<NPTS / MT, 256, SMEM_BYTES>>>(inputs, emb, out);
    vq_final<<<1, 256>>>(out);
}

// round 12
// speedup vs baseline: 1.3232x; 1.3232x over previous
#include <cuda_runtime.h>
#include <math.h>

// VectorQuantizer: N=65536 (64x32x32 BHWC-flat), C=64, K=1024.
// Output (float32): [quantized 4194304][vq_loss 1][indices 65536][perplexity 1]
// Numerics verified bit-exact R1/R5/R7/R9/R10.
// R12 = R10 inner loop, K-split x4 (2048 jobs) + u64 atomicMin merge to cut
// wave-quantization (makespan 2.0 -> 1.75 tile-units). ffma2 rt=3 roofline.

#define NPTS   65536
#define KC     1024
#define CD     64
#define HW     1024
#define MT     128
#define KCH    64
#define NSPLIT 4
#define CHPS   4              // chunks per split (4*64 = 256 codes)
#define NTILE  (NPTS / MT)    // 512
#define XSTRIDE 132
#define ESTRIDE 68
#define ESBUF   (KCH * ESTRIDE)

#define SM_XS   0
#define SM_ES0  (CD * XSTRIDE)           // 8448
#define SM_AS   (SM_ES0 + 2 * ESBUF)     // 17152
#define SM_IDX  (SM_AS + 128)
#define SMEM_FLOATS (SM_IDX + 128)       // 69,632 B -> 2 blocks/SM
#define SMEM_BYTES  (SMEM_FLOATS * 4)

#define OFF_LOSS  4194304
#define OFF_IDX   4194305
#define OFF_PERP  4259841

typedef unsigned long long u64;
typedef unsigned int u32;

__device__ float        g_esq[KC];
__device__ unsigned int g_hist[KC];
__device__ double       g_loss;
__device__ u64          g_win[NPTS];     // (d_bits<<32)|k, merged via atomicMin
__device__ int          g_cnt[NTILE];    // per-tile completion tickets

__device__ __forceinline__ u64 pack_dup(float x) {
    u64 r; asm("mov.b64 %0, {%1, %1};" : "=l"(r) : "f"(x)); return r;
}
__device__ __forceinline__ void unpack2(u64 v, float &lo, float &hi) {
    asm("mov.b64 {%0, %1}, %2;" : "=f"(lo), "=f"(hi) : "l"(v));
}
// packed fp32x2 FMA: each lane is IEEE-rn fp32 FMA (bit-identical to scalar FFMA)
__device__ __forceinline__ void ffma2(u64 &acc, u64 a, u64 b) {
    asm("fma.rn.f32x2 %0, %1, %2, %0;" : "+l"(acc) : "l"(a), "l"(b));
}
__device__ __forceinline__ u32 smem_u32(const void* p) {
    u32 a; asm("{ .reg .u64 t; cvta.to.shared.u64 t, %1; cvt.u32.u64 %0, t; }" : "=r"(a) : "l"(p));
    return a;
}
__device__ __forceinline__ void cp16(u32 dst, const void* src) {
    asm volatile("cp.async.cg.shared.global [%0], [%1], 16;" :: "r"(dst), "l"(src));
}
__device__ __forceinline__ void cp_commit() {
    asm volatile("cp.async.commit_group;" ::: "memory");
}
__device__ __forceinline__ void cp_wait0() {
    asm volatile("cp.async.wait_group 0;" ::: "memory");
}

// ---------------- init ----------------
__global__ void vq_init_hist() {
    int t = blockIdx.x * blockDim.x + threadIdx.x;
    if (t < KC) g_hist[t] = 0u;
    if (t == 0) g_loss = 0.0;
}
__global__ void vq_init_win() {
    int t = blockIdx.x * blockDim.x + threadIdx.x;   // 65,536
    g_win[t] = 0xFFFFFFFFFFFFFFFFULL;
    if (t < NTILE) g_cnt[t] = 0;
}

// ---------------- esq ----------------
__global__ void vq_esq(const float* __restrict__ emb) {
    int k = blockIdx.x * blockDim.x + threadIdx.x;
    if (k < KC) {
        float s = 0.0f;
        const float* er = emb + (size_t)k * CD;
        #pragma unroll
        for (int c = 0; c < CD; ++c) {
            float e = er[c];
            s = __fadd_rn(s, __fmul_rn(e, e));
        }
        g_esq[k] = s;
    }
}

// ------- job = (tile, ksplit): distances + argmin-merge; last job finalizes -------
__global__ void __launch_bounds__(256, 2) vq_main(const float* __restrict__ inputs,
                                                  const float* __restrict__ emb,
                                                  float* __restrict__ out) {
    extern __shared__ float sm[];
    float* xs   = sm + SM_XS;    // [CD][XSTRIDE]  xs[c*XSTRIDE + p]
    float* as_  = sm + SM_AS;    // [128] ||x||^2
    int*   idxs = (int*)(sm + SM_IDX);
    double* red = (double*)(sm + SM_ES0);  // tail scratch (es dead then)
    __shared__ int lastFlag;

    const int t    = threadIdx.x;
    const int tr   = t >> 4;     // 0..15 point group (8 pts each)
    const int tc   = t & 15;     // 0..15 code lane (codes j*16+tc)
    const int tile = blockIdx.x >> 2;
    const int ks   = blockIdx.x & 3;
    const int kc0  = ks * CHPS;  // first chunk (absolute) for this split
    const int n0   = tile * MT;
    const int b    = n0 >> 10;
    const int p0   = n0 & 1023;
    const float* xbase = inputs + (size_t)b * (CD * HW) + p0;

    const u32 es_base = smem_u32(sm + SM_ES0);
    const int skk = t >> 4;
    const int scg = (t & 15) << 2;

    // kick off async stage of first E chunk into buffer 0
    {
        const float* src = emb + (size_t)kc0 * KCH * CD + scg;
        #pragma unroll
        for (int j = 0; j < 4; ++j) {
            int kk = skk + j * 16;
            cp16(es_base + (u32)(kk * ESTRIDE + scg) * 4u, src + (size_t)kk * CD);
        }
    }
    cp_commit();

    // ---- load x tile (transposed into [c][p])
    #pragma unroll
    for (int j = 0; j < 8; ++j) {
        int q  = t + j * 256;
        int c  = q >> 5;
        int i4 = (q & 31) << 2;
        float4 v = *reinterpret_cast<const float4*>(xbase + (size_t)c * HW + i4);
        *reinterpret_cast<float4*>(&xs[c * XSTRIDE + i4]) = v;
    }
    __syncthreads();

    // a = ||x||^2 : strictly sequential fp32
    if (t < MT) {
        float s = 0.0f;
        #pragma unroll
        for (int c = 0; c < CD; ++c) {
            float xv = xs[c * XSTRIDE + t];
            s = __fadd_rn(s, __fmul_rn(xv, xv));
        }
        as_[t] = s;
    }
    __syncthreads();

    float bestv[8];
    int   besti[8];
    #pragma unroll
    for (int i = 0; i < 8; ++i) { bestv[i] = __int_as_float(0x7f800000); besti[i] = 0x7fffffff; }

    #pragma unroll 1
    for (int kcl = 0; kcl < CHPS; ++kcl) {
        const int kc = kc0 + kcl;
        cp_wait0();
        __syncthreads();

        if (kcl + 1 < CHPS) {
            const float* src = emb + (size_t)(kc + 1) * KCH * CD + scg;
            u32 dstb = es_base + (u32)(((kcl + 1) & 1) * ESBUF + scg) * 4u;
            #pragma unroll
            for (int j = 0; j < 4; ++j) {
                int kk = skk + j * 16;
                cp16(dstb + (u32)(kk * ESTRIDE) * 4u, src + (size_t)kk * CD);
            }
        }
        cp_commit();

        const float* es = sm + SM_ES0 + (kcl & 1) * ESBUF;

        u64 acc[4][4];
        #pragma unroll
        for (int j = 0; j < 4; ++j)
            #pragma unroll
            for (int i = 0; i < 4; ++i) acc[j][i] = 0ULL;

        #pragma unroll 4
        for (int c4 = 0; c4 < CD; c4 += 4) {
            float4 ef[4];
            #pragma unroll
            for (int j = 0; j < 4; ++j)
                ef[j] = *reinterpret_cast<const float4*>(&es[(j * 16 + tc) * ESTRIDE + c4]);
            #pragma unroll
            for (int cc = 0; cc < 4; ++cc) {
                const float* xr = &xs[(c4 + cc) * XSTRIDE + tr * 8];
                ulonglong2 Xa = *reinterpret_cast<const ulonglong2*>(xr);
                ulonglong2 Xb = *reinterpret_cast<const ulonglong2*>(xr + 4);
                #pragma unroll
                for (int j = 0; j < 4; ++j) {
                    float ev = (cc == 0) ? ef[j].x : (cc == 1) ? ef[j].y : (cc == 2) ? ef[j].z : ef[j].w;
                    u64 ed = pack_dup(ev);
                    ffma2(acc[j][0], ed, Xa.x);
                    ffma2(acc[j][1], ed, Xa.y);
                    ffma2(acc[j][2], ed, Xb.x);
                    ffma2(acc[j][3], ed, Xb.y);
                }
            }
        }

        // epilogue: d = (a - 2*dot) + esq; k ascending per lane -> strict '<'
        #pragma unroll
        for (int j = 0; j < 4; ++j) {
            int k = kc * KCH + j * 16 + tc;
            float esq = __ldg(&g_esq[k]);
            #pragma unroll
            for (int i = 0; i < 4; ++i) {
                float d0, d1; unpack2(acc[j][i], d0, d1);
                int ii = i * 2;
                float a0 = as_[tr * 8 + ii];
                float a1 = as_[tr * 8 + ii + 1];
                float dd0 = __fadd_rn(__fsub_rn(a0, __fmul_rn(2.0f, d0)), esq);
                float dd1 = __fadd_rn(__fsub_rn(a1, __fmul_rn(2.0f, d1)), esq);
                if (dd0 < bestv[ii])     { bestv[ii]     = dd0; besti[ii]     = k; }
                if (dd1 < bestv[ii + 1]) { bestv[ii + 1] = dd1; besti[ii + 1] = k; }
            }
        }
    }

    // cross-lane argmin over the 16 code lanes (first-index ties)
    #pragma unroll
    for (int off = 1; off < 16; off <<= 1) {
        #pragma unroll
        for (int i = 0; i < 8; ++i) {
            float ov = __shfl_xor_sync(0xffffffffu, bestv[i], off);
            int   oi = __shfl_xor_sync(0xffffffffu, besti[i], off);
            if (ov < bestv[i] || (ov == bestv[i] && oi < besti[i])) { bestv[i] = ov; besti[i] = oi; }
        }
    }
    // merge split winners: d>0 always here, so uint order == float order;
    // ties -> smaller k (== first index) automatically via u64 min.
    if (tc == 0) {
        #pragma unroll
        for (int i = 0; i < 8; ++i) {
            int n = n0 + tr * 8 + i;
            u64 pk = ((u64)__float_as_uint(bestv[i]) << 32) | (u32)besti[i];
            atomicMin(&g_win[n], pk);
        }
        __threadfence();
    }
    __syncthreads();
    if (t == 0) lastFlag = (atomicAdd(&g_cnt[tile], 1) == NSPLIT - 1);
    __syncthreads();
    if (!lastFlag) return;

    // ---- finalizer (exactly one block per tile): winners -> idx/hist/quant/loss ----
    if (t < MT) {
        u64 w = atomicMin(&g_win[n0 + t], 0xFFFFFFFFFFFFFFFFULL);  // coherent read
        int k = (int)(w & 0xFFFFFFFFu);
        idxs[t] = k;
        out[OFF_IDX + n0 + t] = (float)k;
        atomicAdd(&g_hist[k], 1u);
    }
    __syncthreads();

    {
        const int p = t >> 1;
        const int h = t & 1;
        const int c0 = 32 * h;
        const int k = idxs[p];
        const float* eb = emb + (size_t)k * CD + c0;
        float* ob = out + (size_t)(n0 + p) * CD + c0;
        const float* xcol = xs + c0 * XSTRIDE + p;

        double s = 0.0;
        #pragma unroll
        for (int j = 0; j < 8; ++j) {
            float4 qv = __ldg(reinterpret_cast<const float4*>(eb) + j);
            float x0 = xcol[(4 * j + 0) * XSTRIDE];
            float x1 = xcol[(4 * j + 1) * XSTRIDE];
            float x2 = xcol[(4 * j + 2) * XSTRIDE];
            float x3 = xcol[(4 * j + 3) * XSTRIDE];
            float e0 = __fsub_rn(qv.x, x0);
            float e1 = __fsub_rn(qv.y, x1);
            float e2 = __fsub_rn(qv.z, x2);
            float e3 = __fsub_rn(qv.w, x3);
            float4 o;  // straight-through: x + (q - x)
            o.x = __fadd_rn(x0, e0);
            o.y = __fadd_rn(x1, e1);
            o.z = __fadd_rn(x2, e2);
            o.w = __fadd_rn(x3, e3);
            *reinterpret_cast<float4*>(ob + 4 * j) = o;
            s += (double)__fmul_rn(e0, e0) + (double)__fmul_rn(e1, e1)
               + (double)__fmul_rn(e2, e2) + (double)__fmul_rn(e3, e3);
        }
        #pragma unroll
        for (int off = 16; off > 0; off >>= 1)
            s += __shfl_down_sync(0xffffffffu, s, off);
        if ((t & 31) == 0) red[t >> 5] = s;
        __syncthreads();
        if (t == 0) {
            double tot = 0.0;
            #pragma unroll
            for (int w = 0; w < 8; ++w) tot += red[w];
            atomicAdd(&g_loss, tot);
        }
    }
}

// ---------------- finalize ----------------
__global__ void vq_final(float* __restrict__ out) {
    __shared__ double red[256];
    int t = threadIdx.x;
    double s = 0.0;
    for (int k = t; k < KC; k += 256) {
        float cnt = (float)g_hist[k];
        float pr  = __fmul_rn(cnt, 1.0f / 65536.0f);
        float lg  = logf(__fadd_rn(pr, 1e-10f));
        s += (double)__fmul_rn(pr, lg);
    }
    red[t] = s;
    __syncthreads();
    for (int off = 128; off > 0; off >>= 1) {
        if (t < off) red[t] += red[t + off];
        __syncthreads();
    }
    if (t == 0) {
        float m = (float)(g_loss / 4194304.0);
        out[OFF_LOSS] = __fadd_rn(m, __fmul_rn(0.25f, m));
        out[OFF_PERP] = expf(-(float)red[0]);
    }
}

extern "C" void kernel_launch(void* const* d_in, const int* in_sizes, int n_in,
                              void* d_out, int out_size) {
    const float* inputs = (const float*)d_in[0];
    const float* emb    = (const float*)d_in[1];
    if (n_in >= 2 && in_sizes[0] == KC * CD && in_sizes[1] == NPTS * CD) {
        const float* tmp = inputs; inputs = emb; emb = tmp;
    }
    float* out = (float*)d_out;

    cudaFuncSetAttribute(vq_main, cudaFuncAttributeMaxDynamicSharedMemorySize, SMEM_BYTES);

    // launch order keeps vq_main at launch index 3 (ncu captures idx 3)
    vq_init_hist<<<1, 1024>>>();
    vq_init_win<<<NPTS / 256, 256>>>();
    vq_esq<<<KC / 256, 256>>>(emb);
    vq_main<<<NTILE * NSPLIT, 256, SMEM_BYTES>>>(inputs, emb, out);
    vq_final<<<1, 256>>>(out);
}

// round 13
// speedup vs baseline: 1.3361x; 1.0098x over previous
#include <cuda_runtime.h>
#include <math.h>

// VectorQuantizer: N=65536 (64x32x32 BHWC-flat), C=64, K=1024.
// Output (float32): [quantized 4194304][vq_loss 1][indices 65536][perplexity 1]
// Numerics verified bit-exact R1/R5/R7/R9/R10/R12.
// R13 = R12 mainloop (92% of ffma2-rt3 roofline) + launch consolidation:
// pre-kernel fuses init+esq; perplexity/loss fold into the last tile finisher.

#define NPTS   65536
#define KC     1024
#define CD     64
#define HW     1024
#define MT     128
#define KCH    64
#define NSPLIT 4
#define CHPS   4              // chunks per split (4*64 = 256 codes)
#define NTILE  (NPTS / MT)    // 512
#define XSTRIDE 132
#define ESTRIDE 68
#define ESBUF   (KCH * ESTRIDE)

#define SM_XS   0
#define SM_ES0  (CD * XSTRIDE)           // 8448
#define SM_AS   (SM_ES0 + 2 * ESBUF)     // 17152
#define SM_IDX  (SM_AS + 128)
#define SMEM_FLOATS (SM_IDX + 128)       // 69,632 B -> 2 blocks/SM
#define SMEM_BYTES  (SMEM_FLOATS * 4)

#define OFF_LOSS  4194304
#define OFF_IDX   4194305
#define OFF_PERP  4259841

typedef unsigned long long u64;
typedef unsigned int u32;

__device__ float        g_esq[KC];
__device__ unsigned int g_hist[KC];
__device__ double       g_loss;
__device__ u64          g_win[NPTS];     // (d_bits<<32)|k, merged via atomicMin
__device__ int          g_cnt[NTILE];    // per-tile completion tickets
__device__ int          g_done;          // tile-finalizer completion counter

__device__ __forceinline__ u64 pack_dup(float x) {
    u64 r; asm("mov.b64 %0, {%1, %1};" : "=l"(r) : "f"(x)); return r;
}
__device__ __forceinline__ void unpack2(u64 v, float &lo, float &hi) {
    asm("mov.b64 {%0, %1}, %2;" : "=f"(lo), "=f"(hi) : "l"(v));
}
// packed fp32x2 FMA: each lane is IEEE-rn fp32 FMA (bit-identical to scalar FFMA)
__device__ __forceinline__ void ffma2(u64 &acc, u64 a, u64 b) {
    asm("fma.rn.f32x2 %0, %1, %2, %0;" : "+l"(acc) : "l"(a), "l"(b));
}
__device__ __forceinline__ u32 smem_u32(const void* p) {
    u32 a; asm("{ .reg .u64 t; cvta.to.shared.u64 t, %1; cvt.u32.u64 %0, t; }" : "=r"(a) : "l"(p));
    return a;
}
__device__ __forceinline__ void cp16(u32 dst, const void* src) {
    asm volatile("cp.async.cg.shared.global [%0], [%1], 16;" :: "r"(dst), "l"(src));
}
__device__ __forceinline__ void cp_commit() {
    asm volatile("cp.async.commit_group;" ::: "memory");
}
__device__ __forceinline__ void cp_wait0() {
    asm volatile("cp.async.wait_group 0;" ::: "memory");
}

// ---------------- pre: win/hist/cnt/loss init + esq, one launch ----------------
__global__ void vq_pre(const float* __restrict__ emb) {
    int tid = blockIdx.x * blockDim.x + threadIdx.x;   // 65,536
    g_win[tid] = 0xFFFFFFFFFFFFFFFFULL;
    if (tid < KC) {
        float s = 0.0f;
        const float* er = emb + (size_t)tid * CD;
        #pragma unroll
        for (int c = 0; c < CD; ++c) {
            float e = er[c];
            s = __fadd_rn(s, __fmul_rn(e, e));
        }
        g_esq[tid] = s;
        g_hist[tid] = 0u;
    }
    if (tid < NTILE) g_cnt[tid] = 0;
    if (tid == 0) { g_loss = 0.0; g_done = 0; }
}

// ------- job = (tile, ksplit): distances + argmin-merge; last job finalizes;
//         the globally-last tile finisher also emits loss + perplexity -------
__global__ void __launch_bounds__(256, 2) vq_main(const float* __restrict__ inputs,
                                                  const float* __restrict__ emb,
                                                  float* __restrict__ out) {
    extern __shared__ float sm[];
    float* xs   = sm + SM_XS;    // [CD][XSTRIDE]  xs[c*XSTRIDE + p]
    float* as_  = sm + SM_AS;    // [128] ||x||^2
    int*   idxs = (int*)(sm + SM_IDX);
    double* red = (double*)(sm + SM_ES0);  // tail scratch (es dead then)
    __shared__ int lastFlag;
    __shared__ int globalLast;

    const int t    = threadIdx.x;
    const int tr   = t >> 4;     // 0..15 point group (8 pts each)
    const int tc   = t & 15;     // 0..15 code lane (codes j*16+tc)
    const int tile = blockIdx.x >> 2;
    const int ks   = blockIdx.x & 3;
    const int kc0  = ks * CHPS;
    const int n0   = tile * MT;
    const int b    = n0 >> 10;
    const int p0   = n0 & 1023;
    const float* xbase = inputs + (size_t)b * (CD * HW) + p0;

    const u32 es_base = smem_u32(sm + SM_ES0);
    const int skk = t >> 4;
    const int scg = (t & 15) << 2;

    // kick off async stage of first E chunk into buffer 0
    {
        const float* src = emb + (size_t)kc0 * KCH * CD + scg;
        #pragma unroll
        for (int j = 0; j < 4; ++j) {
            int kk = skk + j * 16;
            cp16(es_base + (u32)(kk * ESTRIDE + scg) * 4u, src + (size_t)kk * CD);
        }
    }
    cp_commit();

    // ---- load x tile (transposed into [c][p])
    #pragma unroll
    for (int j = 0; j < 8; ++j) {
        int q  = t + j * 256;
        int c  = q >> 5;
        int i4 = (q & 31) << 2;
        float4 v = *reinterpret_cast<const float4*>(xbase + (size_t)c * HW + i4);
        *reinterpret_cast<float4*>(&xs[c * XSTRIDE + i4]) = v;
    }
    __syncthreads();

    // a = ||x||^2 : strictly sequential fp32
    if (t < MT) {
        float s = 0.0f;
        #pragma unroll
        for (int c = 0; c < CD; ++c) {
            float xv = xs[c * XSTRIDE + t];
            s = __fadd_rn(s, __fmul_rn(xv, xv));
        }
        as_[t] = s;
    }
    __syncthreads();

    float bestv[8];
    int   besti[8];
    #pragma unroll
    for (int i = 0; i < 8; ++i) { bestv[i] = __int_as_float(0x7f800000); besti[i] = 0x7fffffff; }

    #pragma unroll 1
    for (int kcl = 0; kcl < CHPS; ++kcl) {
        const int kc = kc0 + kcl;
        cp_wait0();
        __syncthreads();

        if (kcl + 1 < CHPS) {
            const float* src = emb + (size_t)(kc + 1) * KCH * CD + scg;
            u32 dstb = es_base + (u32)(((kcl + 1) & 1) * ESBUF + scg) * 4u;
            #pragma unroll
            for (int j = 0; j < 4; ++j) {
                int kk = skk + j * 16;
                cp16(dstb + (u32)(kk * ESTRIDE) * 4u, src + (size_t)kk * CD);
            }
        }
        cp_commit();

        const float* es = sm + SM_ES0 + (kcl & 1) * ESBUF;

        u64 acc[4][4];
        #pragma unroll
        for (int j = 0; j < 4; ++j)
            #pragma unroll
            for (int i = 0; i < 4; ++i) acc[j][i] = 0ULL;

        #pragma unroll 4
        for (int c4 = 0; c4 < CD; c4 += 4) {
            float4 ef[4];
            #pragma unroll
            for (int j = 0; j < 4; ++j)
                ef[j] = *reinterpret_cast<const float4*>(&es[(j * 16 + tc) * ESTRIDE + c4]);
            #pragma unroll
            for (int cc = 0; cc < 4; ++cc) {
                const float* xr = &xs[(c4 + cc) * XSTRIDE + tr * 8];
                ulonglong2 Xa = *reinterpret_cast<const ulonglong2*>(xr);
                ulonglong2 Xb = *reinterpret_cast<const ulonglong2*>(xr + 4);
                #pragma unroll
                for (int j = 0; j < 4; ++j) {
                    float ev = (cc == 0) ? ef[j].x : (cc == 1) ? ef[j].y : (cc == 2) ? ef[j].z : ef[j].w;
                    u64 ed = pack_dup(ev);
                    ffma2(acc[j][0], ed, Xa.x);
                    ffma2(acc[j][1], ed, Xa.y);
                    ffma2(acc[j][2], ed, Xb.x);
                    ffma2(acc[j][3], ed, Xb.y);
                }
            }
        }

        // epilogue: d = (a - 2*dot) + esq; k ascending per lane -> strict '<'
        #pragma unroll
        for (int j = 0; j < 4; ++j) {
            int k = kc * KCH + j * 16 + tc;
            float esq = __ldg(&g_esq[k]);
            #pragma unroll
            for (int i = 0; i < 4; ++i) {
                float d0, d1; unpack2(acc[j][i], d0, d1);
                int ii = i * 2;
                float a0 = as_[tr * 8 + ii];
                float a1 = as_[tr * 8 + ii + 1];
                float dd0 = __fadd_rn(__fsub_rn(a0, __fmul_rn(2.0f, d0)), esq);
                float dd1 = __fadd_rn(__fsub_rn(a1, __fmul_rn(2.0f, d1)), esq);
                if (dd0 < bestv[ii])     { bestv[ii]     = dd0; besti[ii]     = k; }
                if (dd1 < bestv[ii + 1]) { bestv[ii + 1] = dd1; besti[ii + 1] = k; }
            }
        }
    }

    // cross-lane argmin over the 16 code lanes (first-index ties)
    #pragma unroll
    for (int off = 1; off < 16; off <<= 1) {
        #pragma unroll
        for (int i = 0; i < 8; ++i) {
            float ov = __shfl_xor_sync(0xffffffffu, bestv[i], off);
            int   oi = __shfl_xor_sync(0xffffffffu, besti[i], off);
            if (ov < bestv[i] || (ov == bestv[i] && oi < besti[i])) { bestv[i] = ov; besti[i] = oi; }
        }
    }
    // merge split winners: d>0 always here, so uint order == float order;
    // ties -> smaller k (== first index) automatically via u64 min.
    if (tc == 0) {
        #pragma unroll
        for (int i = 0; i < 8; ++i) {
            int n = n0 + tr * 8 + i;
            u64 pk = ((u64)__float_as_uint(bestv[i]) << 32) | (u32)besti[i];
            atomicMin(&g_win[n], pk);
        }
        __threadfence();
    }
    __syncthreads();
    if (t == 0) lastFlag = (atomicAdd(&g_cnt[tile], 1) == NSPLIT - 1);
    __syncthreads();
    if (!lastFlag) return;

    // ---- tile finalizer (one block per tile): winners -> idx/hist/quant/loss ----
    if (t < MT) {
        u64 w = atomicMin(&g_win[n0 + t], 0xFFFFFFFFFFFFFFFFULL);  // coherent read
        int k = (int)(w & 0xFFFFFFFFu);
        idxs[t] = k;
        out[OFF_IDX + n0 + t] = (float)k;
        atomicAdd(&g_hist[k], 1u);
    }
    __syncthreads();

    {
        const int p = t >> 1;
        const int h = t & 1;
        const int c0 = 32 * h;
        const int k = idxs[p];
        const float* eb = emb + (size_t)k * CD + c0;
        float* ob = out + (size_t)(n0 + p) * CD + c0;
        const float* xcol = xs + c0 * XSTRIDE + p;

        double s = 0.0;
        #pragma unroll
        for (int j = 0; j < 8; ++j) {
            float4 qv = __ldg(reinterpret_cast<const float4*>(eb) + j);
            float x0 = xcol[(4 * j + 0) * XSTRIDE];
            float x1 = xcol[(4 * j + 1) * XSTRIDE];
            float x2 = xcol[(4 * j + 2) * XSTRIDE];
            float x3 = xcol[(4 * j + 3) * XSTRIDE];
            float e0 = __fsub_rn(qv.x, x0);
            float e1 = __fsub_rn(qv.y, x1);
            float e2 = __fsub_rn(qv.z, x2);
            float e3 = __fsub_rn(qv.w, x3);
            float4 o;  // straight-through: x + (q - x)
            o.x = __fadd_rn(x0, e0);
            o.y = __fadd_rn(x1, e1);
            o.z = __fadd_rn(x2, e2);
            o.w = __fadd_rn(x3, e3);
            *reinterpret_cast<float4*>(ob + 4 * j) = o;
            s += (double)__fmul_rn(e0, e0) + (double)__fmul_rn(e1, e1)
               + (double)__fmul_rn(e2, e2) + (double)__fmul_rn(e3, e3);
        }
        #pragma unroll
        for (int off = 16; off > 0; off >>= 1)
            s += __shfl_down_sync(0xffffffffu, s, off);
        if ((t & 31) == 0) red[t >> 5] = s;
        __syncthreads();
        if (t == 0) {
            double tot = 0.0;
            #pragma unroll
            for (int w = 0; w < 8; ++w) tot += red[w];
            atomicAdd(&g_loss, tot);
        }
    }

    // ---- global last-finisher emits loss + perplexity ----
    __threadfence();
    __syncthreads();
    if (t == 0) globalLast = (atomicAdd(&g_done, 1) == NTILE - 1);
    __syncthreads();
    if (!globalLast) return;

    {
        double s = 0.0;
        for (int k = t; k < KC; k += 256) {
            float cnt = (float)__ldcg(&g_hist[k]);   // L2-coherent (post-fence)
            float pr  = __fmul_rn(cnt, 1.0f / 65536.0f);
            float lg  = logf(__fadd_rn(pr, 1e-10f));
            s += (double)__fmul_rn(pr, lg);
        }
        #pragma unroll
        for (int off = 16; off > 0; off >>= 1)
            s += __shfl_down_sync(0xffffffffu, s, off);
        if ((t & 31) == 0) red[32 + (t >> 5)] = s;
        __syncthreads();
        if (t == 0) {
            double S = 0.0;
            #pragma unroll
            for (int w = 0; w < 8; ++w) S += red[32 + w];
            double lossSum = atomicAdd(&g_loss, 0.0);   // coherent read
            float m = (float)(lossSum / 4194304.0);
            out[OFF_LOSS] = __fadd_rn(m, __fmul_rn(0.25f, m));
            out[OFF_PERP] = expf(-(float)S);
        }
    }
}

extern "C" void kernel_launch(void* const* d_in, const int* in_sizes, int n_in,
                              void* d_out, int out_size) {
    const float* inputs = (const float*)d_in[0];
    const float* emb    = (const float*)d_in[1];
    if (n_in >= 2 && in_sizes[0] == KC * CD && in_sizes[1] == NPTS * CD) {
        const float* tmp = inputs; inputs = emb; emb = tmp;
    }
    float* out = (float*)d_out;

    cudaFuncSetAttribute(vq_main, cudaFuncAttributeMaxDynamicSharedMemorySize, SMEM_BYTES);

    vq_pre<<<NPTS / 256, 256>>>(emb);
    vq_main<<<NTILE * NSPLIT, 256, SMEM_BYTES>>>(inputs, emb, out);
}

// round 14
// speedup vs baseline: 1.3654x; 1.0219x over previous
#include <cuda_runtime.h>
#include <math.h>

// VectorQuantizer: N=65536 (64x32x32 BHWC-flat), C=64, K=1024.
// Output (float32): [quantized 4194304][vq_loss 1][indices 65536][perplexity 1]
// Numerics verified bit-exact R1/R5/R7/R9/R10/R12/R13.
// R14 = R13 with packed-f32x2 epilogue:
//   rn(a - rn(2*dot)) == fma.rn(dot,-2,a)  (2*dot exact) -> 1 packed fma
//   + packed add of esq. Bit-identical distances, ~6 fewer instrs per pair.

#define NPTS   65536
#define KC     1024
#define CD     64
#define HW     1024
#define MT     128
#define KCH    64
#define NSPLIT 4
#define CHPS   4              // chunks per split (4*64 = 256 codes)
#define NTILE  (NPTS / MT)    // 512
#define XSTRIDE 132
#define ESTRIDE 68
#define ESBUF   (KCH * ESTRIDE)

#define SM_XS   0
#define SM_ES0  (CD * XSTRIDE)           // 8448
#define SM_AS   (SM_ES0 + 2 * ESBUF)     // 17152
#define SM_IDX  (SM_AS + 128)
#define SMEM_FLOATS (SM_IDX + 128)       // 69,632 B -> 2 blocks/SM
#define SMEM_BYTES  (SMEM_FLOATS * 4)

#define OFF_LOSS  4194304
#define OFF_IDX   4194305
#define OFF_PERP  4259841

typedef unsigned long long u64;
typedef unsigned int u32;

__device__ float        g_esq[KC];
__device__ unsigned int g_hist[KC];
__device__ double       g_loss;
__device__ u64          g_win[NPTS];     // (d_bits<<32)|k, merged via atomicMin
__device__ int          g_cnt[NTILE];    // per-tile completion tickets
__device__ int          g_done;          // tile-finalizer completion counter

__device__ __forceinline__ u64 pack_dup(float x) {
    u64 r; asm("mov.b64 %0, {%1, %1};" : "=l"(r) : "f"(x)); return r;
}
__device__ __forceinline__ void unpack2(u64 v, float &lo, float &hi) {
    asm("mov.b64 {%0, %1}, %2;" : "=f"(lo), "=f"(hi) : "l"(v));
}
// packed fp32x2 FMA: each lane is IEEE-rn fp32 FMA (bit-identical to scalar FFMA)
__device__ __forceinline__ void ffma2(u64 &acc, u64 a, u64 b) {
    asm("fma.rn.f32x2 %0, %1, %2, %0;" : "+l"(acc) : "l"(a), "l"(b));
}
__device__ __forceinline__ u64 ffma2_3(u64 a, u64 b, u64 c) {
    u64 r; asm("fma.rn.f32x2 %0, %1, %2, %3;" : "=l"(r) : "l"(a), "l"(b), "l"(c)); return r;
}
__device__ __forceinline__ u64 fadd2(u64 a, u64 b) {
    u64 r; asm("add.rn.f32x2 %0, %1, %2;" : "=l"(r) : "l"(a), "l"(b)); return r;
}
__device__ __forceinline__ u32 smem_u32(const void* p) {
    u32 a; asm("{ .reg .u64 t; cvta.to.shared.u64 t, %1; cvt.u32.u64 %0, t; }" : "=r"(a) : "l"(p));
    return a;
}
__device__ __forceinline__ void cp16(u32 dst, const void* src) {
    asm volatile("cp.async.cg.shared.global [%0], [%1], 16;" :: "r"(dst), "l"(src));
}
__device__ __forceinline__ void cp_commit() {
    asm volatile("cp.async.commit_group;" ::: "memory");
}
__device__ __forceinline__ void cp_wait0() {
    asm volatile("cp.async.wait_group 0;" ::: "memory");
}

// ---------------- pre: win/hist/cnt/loss init + esq, one launch ----------------
__global__ void vq_pre(const float* __restrict__ emb) {
    int tid = blockIdx.x * blockDim.x + threadIdx.x;   // 65,536
    g_win[tid] = 0xFFFFFFFFFFFFFFFFULL;
    if (tid < KC) {
        float s = 0.0f;
        const float* er = emb + (size_t)tid * CD;
        #pragma unroll
        for (int c = 0; c < CD; ++c) {
            float e = er[c];
            s = __fadd_rn(s, __fmul_rn(e, e));
        }
        g_esq[tid] = s;
        g_hist[tid] = 0u;
    }
    if (tid < NTILE) g_cnt[tid] = 0;
    if (tid == 0) { g_loss = 0.0; g_done = 0; }
}

// ------- job = (tile, ksplit): distances + argmin-merge; last job finalizes;
//         the globally-last tile finisher also emits loss + perplexity -------
__global__ void __launch_bounds__(256, 2) vq_main(const float* __restrict__ inputs,
                                                  const float* __restrict__ emb,
                                                  float* __restrict__ out) {
    extern __shared__ float sm[];
    float* xs   = sm + SM_XS;    // [CD][XSTRIDE]  xs[c*XSTRIDE + p]
    float* as_  = sm + SM_AS;    // [128] ||x||^2 (point-pair aligned)
    int*   idxs = (int*)(sm + SM_IDX);
    double* red = (double*)(sm + SM_ES0);  // tail scratch (es dead then)
    __shared__ int lastFlag;
    __shared__ int globalLast;

    const int t    = threadIdx.x;
    const int tr   = t >> 4;     // 0..15 point group (8 pts each)
    const int tc   = t & 15;     // 0..15 code lane (codes j*16+tc)
    const int tile = blockIdx.x >> 2;
    const int ks   = blockIdx.x & 3;
    const int kc0  = ks * CHPS;
    const int n0   = tile * MT;
    const int b    = n0 >> 10;
    const int p0   = n0 & 1023;
    const float* xbase = inputs + (size_t)b * (CD * HW) + p0;

    const u32 es_base = smem_u32(sm + SM_ES0);
    const int skk = t >> 4;
    const int scg = (t & 15) << 2;

    // kick off async stage of first E chunk into buffer 0
    {
        const float* src = emb + (size_t)kc0 * KCH * CD + scg;
        #pragma unroll
        for (int j = 0; j < 4; ++j) {
            int kk = skk + j * 16;
            cp16(es_base + (u32)(kk * ESTRIDE + scg) * 4u, src + (size_t)kk * CD);
        }
    }
    cp_commit();

    // ---- load x tile (transposed into [c][p])
    #pragma unroll
    for (int j = 0; j < 8; ++j) {
        int q  = t + j * 256;
        int c  = q >> 5;
        int i4 = (q & 31) << 2;
        float4 v = *reinterpret_cast<const float4*>(xbase + (size_t)c * HW + i4);
        *reinterpret_cast<float4*>(&xs[c * XSTRIDE + i4]) = v;
    }
    __syncthreads();

    // a = ||x||^2 : strictly sequential fp32
    if (t < MT) {
        float s = 0.0f;
        #pragma unroll
        for (int c = 0; c < CD; ++c) {
            float xv = xs[c * XSTRIDE + t];
            s = __fadd_rn(s, __fmul_rn(xv, xv));
        }
        as_[t] = s;
    }
    __syncthreads();

    float bestv[8];
    int   besti[8];
    #pragma unroll
    for (int i = 0; i < 8; ++i) { bestv[i] = __int_as_float(0x7f800000); besti[i] = 0x7fffffff; }

    const u64 neg2 = pack_dup(-2.0f);

    #pragma unroll 1
    for (int kcl = 0; kcl < CHPS; ++kcl) {
        const int kc = kc0 + kcl;
        cp_wait0();
        __syncthreads();

        if (kcl + 1 < CHPS) {
            const float* src = emb + (size_t)(kc + 1) * KCH * CD + scg;
            u32 dstb = es_base + (u32)(((kcl + 1) & 1) * ESBUF + scg) * 4u;
            #pragma unroll
            for (int j = 0; j < 4; ++j) {
                int kk = skk + j * 16;
                cp16(dstb + (u32)(kk * ESTRIDE) * 4u, src + (size_t)kk * CD);
            }
        }
        cp_commit();

        const float* es = sm + SM_ES0 + (kcl & 1) * ESBUF;

        u64 acc[4][4];
        #pragma unroll
        for (int j = 0; j < 4; ++j)
            #pragma unroll
            for (int i = 0; i < 4; ++i) acc[j][i] = 0ULL;

        #pragma unroll 4
        for (int c4 = 0; c4 < CD; c4 += 4) {
            float4 ef[4];
            #pragma unroll
            for (int j = 0; j < 4; ++j)
                ef[j] = *reinterpret_cast<const float4*>(&es[(j * 16 + tc) * ESTRIDE + c4]);
            #pragma unroll
            for (int cc = 0; cc < 4; ++cc) {
                const float* xr = &xs[(c4 + cc) * XSTRIDE + tr * 8];
                ulonglong2 Xa = *reinterpret_cast<const ulonglong2*>(xr);
                ulonglong2 Xb = *reinterpret_cast<const ulonglong2*>(xr + 4);
                #pragma unroll
                for (int j = 0; j < 4; ++j) {
                    float ev = (cc == 0) ? ef[j].x : (cc == 1) ? ef[j].y : (cc == 2) ? ef[j].z : ef[j].w;
                    u64 ed = pack_dup(ev);
                    ffma2(acc[j][0], ed, Xa.x);
                    ffma2(acc[j][1], ed, Xa.y);
                    ffma2(acc[j][2], ed, Xb.x);
                    ffma2(acc[j][3], ed, Xb.y);
                }
            }
        }

        // ---- packed epilogue: dd2 = (a2 + (-2)*dot2) + esq2  (bit-identical:
        // 2*dot exact => fma.rn(dot,-2,a) == rn(a - rn(2*dot)); then add.rn esq)
        const u64* a2 = reinterpret_cast<const u64*>(&as_[tr * 8]);  // 4 point-pairs
        u64 A0 = a2[0], A1 = a2[1], A2 = a2[2], A3 = a2[3];
        #pragma unroll
        for (int j = 0; j < 4; ++j) {
            int k = kc * KCH + j * 16 + tc;
            u64 esq2 = pack_dup(__ldg(&g_esq[k]));
            #pragma unroll
            for (int i = 0; i < 4; ++i) {
                u64 Ai = (i == 0) ? A0 : (i == 1) ? A1 : (i == 2) ? A2 : A3;
                u64 dd2 = fadd2(ffma2_3(acc[j][i], neg2, Ai), esq2);
                float dd0, dd1; unpack2(dd2, dd0, dd1);
                int ii = i * 2;
                if (dd0 < bestv[ii])     { bestv[ii]     = dd0; besti[ii]     = k; }
                if (dd1 < bestv[ii + 1]) { bestv[ii + 1] = dd1; besti[ii + 1] = k; }
            }
        }
    }

    // cross-lane argmin over the 16 code lanes (first-index ties)
    #pragma unroll
    for (int off = 1; off < 16; off <<= 1) {
        #pragma unroll
        for (int i = 0; i < 8; ++i) {
            float ov = __shfl_xor_sync(0xffffffffu, bestv[i], off);
            int   oi = __shfl_xor_sync(0xffffffffu, besti[i], off);
            if (ov < bestv[i] || (ov == bestv[i] && oi < besti[i])) { bestv[i] = ov; besti[i] = oi; }
        }
    }
    // merge split winners: d>0 always here, so uint order == float order;
    // ties -> smaller k (== first index) automatically via u64 min.
    if (tc == 0) {
        #pragma unroll
        for (int i = 0; i < 8; ++i) {
            int n = n0 + tr * 8 + i;
            u64 pk = ((u64)__float_as_uint(bestv[i]) << 32) | (u32)besti[i];
            atomicMin(&g_win[n], pk);
        }
        __threadfence();
    }
    __syncthreads();
    if (t == 0) lastFlag = (atomicAdd(&g_cnt[tile], 1) == NSPLIT - 1);
    __syncthreads();
    if (!lastFlag) return;

    // ---- tile finalizer (one block per tile): winners -> idx/hist/quant/loss ----
    if (t < MT) {
        u64 w = atomicMin(&g_win[n0 + t], 0xFFFFFFFFFFFFFFFFULL);  // coherent read
        int k = (int)(w & 0xFFFFFFFFu);
        idxs[t] = k;
        out[OFF_IDX + n0 + t] = (float)k;
        atomicAdd(&g_hist[k], 1u);
    }
    __syncthreads();

    {
        const int p = t >> 1;
        const int h = t & 1;
        const int c0 = 32 * h;
        const int k = idxs[p];
        const float* eb = emb + (size_t)k * CD + c0;
        float* ob = out + (size_t)(n0 + p) * CD + c0;
        const float* xcol = xs + c0 * XSTRIDE + p;

        double s = 0.0;
        #pragma unroll
        for (int j = 0; j < 8; ++j) {
            float4 qv = __ldg(reinterpret_cast<const float4*>(eb) + j);
            float x0 = xcol[(4 * j + 0) * XSTRIDE];
            float x1 = xcol[(4 * j + 1) * XSTRIDE];
            float x2 = xcol[(4 * j + 2) * XSTRIDE];
            float x3 = xcol[(4 * j + 3) * XSTRIDE];
            float e0 = __fsub_rn(qv.x, x0);
            float e1 = __fsub_rn(qv.y, x1);
            float e2 = __fsub_rn(qv.z, x2);
            float e3 = __fsub_rn(qv.w, x3);
            float4 o;  // straight-through: x + (q - x)
            o.x = __fadd_rn(x0, e0);
            o.y = __fadd_rn(x1, e1);
            o.z = __fadd_rn(x2, e2);
            o.w = __fadd_rn(x3, e3);
            *reinterpret_cast<float4*>(ob + 4 * j) = o;
            s += (double)__fmul_rn(e0, e0) + (double)__fmul_rn(e1, e1)
               + (double)__fmul_rn(e2, e2) + (double)__fmul_rn(e3, e3);
        }
        #pragma unroll
        for (int off = 16; off > 0; off >>= 1)
            s += __shfl_down_sync(0xffffffffu, s, off);
        if ((t & 31) == 0) red[t >> 5] = s;
        __syncthreads();
        if (t == 0) {
            double tot = 0.0;
            #pragma unroll
            for (int w = 0; w < 8; ++w) tot += red[w];
            atomicAdd(&g_loss, tot);
        }
    }

    // ---- global last-finisher emits loss + perplexity ----
    __threadfence();
    __syncthreads();
    if (t == 0) globalLast = (atomicAdd(&g_done, 1) == NTILE - 1);
    __syncthreads();
    if (!globalLast) return;

    {
        double s = 0.0;
        for (int k = t; k < KC; k += 256) {
            float cnt = (float)__ldcg(&g_hist[k]);   // L2-coherent (post-fence)
            float pr  = __fmul_rn(cnt, 1.0f / 65536.0f);
            float lg  = logf(__fadd_rn(pr, 1e-10f));
            s += (double)__fmul_rn(pr, lg);
        }
        #pragma unroll
        for (int off = 16; off > 0; off >>= 1)
            s += __shfl_down_sync(0xffffffffu, s, off);
        if ((t & 31) == 0) red[32 + (t >> 5)] = s;
        __syncthreads();
        if (t == 0) {
            double S = 0.0;
            #pragma unroll
            for (int w = 0; w < 8; ++w) S += red[32 + w];
            double lossSum = atomicAdd(&g_loss, 0.0);   // coherent read
            float m = (float)(lossSum / 4194304.0);
            out[OFF_LOSS] = __fadd_rn(m, __fmul_rn(0.25f, m));
            out[OFF_PERP] = expf(-(float)S);
        }
    }
}

extern "C" void kernel_launch(void* const* d_in, const int* in_sizes, int n_in,
                              void* d_out, int out_size) {
    const float* inputs = (const float*)d_in[0];
    const float* emb    = (const float*)d_in[1];
    if (n_in >= 2 && in_sizes[0] == KC * CD && in_sizes[1] == NPTS * CD) {
        const float* tmp = inputs; inputs = emb; emb = tmp;
    }
    float* out = (float*)d_out;

    cudaFuncSetAttribute(vq_main, cudaFuncAttributeMaxDynamicSharedMemorySize, SMEM_BYTES);

    vq_pre<<<NPTS / 256, 256>>>(emb);
    vq_main<<<NTILE * NSPLIT, 256, SMEM_BYTES>>>(inputs, emb, out);
}